// round 15
// baseline (speedup 1.0000x reference)
#include <cuda_runtime.h>
#include <cstdint>

#define NPTS   300000
#define NPAIRS 100000
#define KOFF   27
#define CIN    32
#define COUT   64
#define NGRP   8
#define NB     5            // batches (of 32 pairs) per warp
#define NBATCH 3125         // 32-pair batches per k-offset (100000/32)
#define ROWPAD 36           // stage row stride in floats (conflict-free LDS)

// ---- scratch (no allocations allowed) ----
__device__ float g_sum[NGRP];
__device__ float g_sq[NGRP];
__device__ int   g_is64;

// tf32 round-to-nearest-even via integer ops (no cvt.*.tf32 instruction):
// keep top 19 bits (1s + 8e + 10m), RN-even on the 13 dropped bits.
__device__ __forceinline__ uint32_t to_tf32(float f) {
    uint32_t u = __float_as_uint(f);
    u += 0xFFFu + ((u >> 13) & 1u);
    return u & 0xFFFFE000u;
}

__device__ __forceinline__ void mma_tf32(float* c, const uint32_t* a,
                                         uint32_t b0, uint32_t b1) {
    asm volatile(
        "mma.sync.aligned.m16n8k8.row.col.f32.tf32.tf32.f32 "
        "{%0,%1,%2,%3}, {%4,%5,%6,%7}, {%8,%9}, {%0,%1,%2,%3};"
        : "+f"(c[0]), "+f"(c[1]), "+f"(c[2]), "+f"(c[3])
        : "r"(a[0]), "r"(a[1]), "r"(a[2]), "r"(a[3]), "r"(b0), "r"(b1));
}

__device__ __forceinline__ void red_add_v2(float* addr, float x, float y) {
    asm volatile("red.global.add.v2.f32 [%0], {%1, %2};"
                 :: "l"(addr), "f"(x), "f"(y) : "memory");
}

__device__ __forceinline__ void cp_async16(unsigned int saddr, const void* gptr) {
    asm volatile("cp.async.cg.shared.global [%0], [%1], 16;"
                 :: "r"(saddr), "l"(gptr) : "memory");
}
#define CP_COMMIT() asm volatile("cp.async.commit_group;" ::: "memory")
#define CP_WAIT1()  asm volatile("cp.async.wait_group 1;"  ::: "memory")

// zero output + scratch; block 0 also detects int64-vs-int32 indices
// (jax x64 ambiguity: if int64, high words of first 4K entries are all 0).
__global__ void zero_kernel(float4* __restrict__ out, int n4,
                            const unsigned int* __restrict__ idx32) {
    int i = blockIdx.x * blockDim.x + threadIdx.x;
    if (i < n4) out[i] = make_float4(0.f, 0.f, 0.f, 0.f);
    if (blockIdx.x == 0) {
        __shared__ int s_any;
        if (threadIdx.x == 0) s_any = 0;
        __syncthreads();
        unsigned int v = 0;
        for (int t = threadIdx.x; t < 2048; t += blockDim.x)
            v |= idx32[2 * t + 1];
        if (v) atomicOr(&s_any, 1);
        __syncthreads();
        if (threadIdx.x == 0) g_is64 = (s_any == 0) ? 1 : 0;
        if (threadIdx.x < NGRP) { g_sum[threadIdx.x] = 0.f; g_sq[threadIdx.x] = 0.f; }
    }
}

__device__ __forceinline__ int load_idx(const void* p, long long pos, int is64) {
    if (is64) return (int)((const long long*)p)[pos];
    return ((const int*)p)[pos];
}

// Sparse conv on tensor cores. Each warp owns NB=5 consecutive 32-pair
// batches; per batch, C[32,64] = A[32 pairs, 32 cin] x W[32,64] via 64
// mma.sync.m16n8k8.tf32 (2 HMMA/record). cp.async double-buffer streams the
// next batch's 32 feature rows while the current computes. Stage rows padded
// to ROWPAD=36 floats -> conflict-free A-fragment LDS. Scatter: C fragments
// map to (row, 2 adjacent cols) -> red.global.add.v2.f32 from all lanes.
__global__ __launch_bounds__(128, 4)
void conv_kernel(const float* __restrict__ feats,
                 const float* __restrict__ weight,
                 const void*  __restrict__ in_idx,
                 const void*  __restrict__ out_idx,
                 float*       __restrict__ out) {
    const int k    = blockIdx.y;
    const int lane = threadIdx.x & 31;
    const int warp = threadIdx.x >> 5;

    __shared__ float stage[4][2][32 * ROWPAD];   // warp x buffer x rows (padded)

    const int b0 = (blockIdx.x * 4 + warp) * NB;
    if (b0 >= NBATCH) return;

    const int gid = lane >> 2;       // 0..7  (fragment group id)
    const int tig = lane & 3;        // 0..3  (thread in group)

    // B fragments (weights, tf32), once per warp: B[kk][nn] covers
    // k rows kk*8..kk*8+7, n cols nn*8..nn*8+7 of W[cin][cout].
    const float* wk = weight + (long long)k * CIN * COUT;
    uint32_t Bf[4][8][2];
#pragma unroll
    for (int kk = 0; kk < 4; kk++)
#pragma unroll
        for (int nn = 0; nn < 8; nn++) {
            Bf[kk][nn][0] = to_tf32(__ldg(wk + (kk*8 + tig)     * COUT + nn*8 + gid));
            Bf[kk][nn][1] = to_tf32(__ldg(wk + (kk*8 + tig + 4) * COUT + nn*8 + gid));
        }

    const int is64 = g_is64;
    const long long base = (long long)k * NPAIRS;
    const int sub = lane >> 3;          // row-within-group of 4 (cp.async)
    const int q   = lane & 7;           // 16B chunk within row (cp.async)
    const unsigned int sb0 = (unsigned int)__cvta_generic_to_shared(&stage[warp][0][0]);
    const unsigned int sb1 = (unsigned int)__cvta_generic_to_shared(&stage[warp][1][0]);

    auto idx_pos = [&](int b) -> long long {
        int bc = (b < NBATCH) ? b : NBATCH - 1;
        return base + bc * 32 + lane;
    };
    auto issue = [&](int ir, unsigned int sbuf) {
#pragma unroll
        for (int g = 0; g < 8; g++) {
            const int r    = 4 * g + sub;
            const int irow = __shfl_sync(0xffffffffu, ir, r);
            cp_async16(sbuf + r * (ROWPAD * 4) + q * 16,
                       (const char*)(feats + (long long)irow * CIN) + q * 16);
        }
    };

    // ---- prologue ----
    int cur_ir = load_idx(in_idx,  idx_pos(b0), is64);
    int cur_or = load_idx(out_idx, idx_pos(b0), is64);
    issue(cur_ir, sb0);
    CP_COMMIT();
    int nxt_ir = load_idx(in_idx,  idx_pos(b0 + 1), is64);
    int nxt_or = load_idx(out_idx, idx_pos(b0 + 1), is64);

    unsigned int sbuf_cur = sb0, sbuf_nxt = sb1;
    const float* st_cur = &stage[warp][0][0];
    const float* st_nxt = &stage[warp][1][0];

    for (int t = 0; t < NB; t++) {
        const int b = b0 + t;
        if (b >= NBATCH) break;

        if (t + 1 < NB && b + 1 < NBATCH) issue(nxt_ir, sbuf_nxt);
        CP_COMMIT();

        int pf_ir = load_idx(in_idx,  idx_pos(b + 2), is64);
        int pf_or = load_idx(out_idx, idx_pos(b + 2), is64);

        CP_WAIT1();
        __syncwarp();

        // ---- compute batch t on tensor cores, N in two halves ----
        const int orow = cur_or;
#pragma unroll
        for (int half = 0; half < 2; half++) {
            float c[2][4][4];
#pragma unroll
            for (int m = 0; m < 2; m++)
#pragma unroll
                for (int nn = 0; nn < 4; nn++)
#pragma unroll
                    for (int e = 0; e < 4; e++) c[m][nn][e] = 0.f;

#pragma unroll
            for (int kk = 0; kk < 4; kk++) {
                uint32_t a[2][4];
#pragma unroll
                for (int m = 0; m < 2; m++) {
                    const int r  = m * 16 + gid;
                    const int cb = kk * 8 + tig;
                    a[m][0] = to_tf32(st_cur[r       * ROWPAD + cb]);
                    a[m][1] = to_tf32(st_cur[(r + 8) * ROWPAD + cb]);
                    a[m][2] = to_tf32(st_cur[r       * ROWPAD + cb + 4]);
                    a[m][3] = to_tf32(st_cur[(r + 8) * ROWPAD + cb + 4]);
                }
#pragma unroll
                for (int m = 0; m < 2; m++)
#pragma unroll
                    for (int nn = 0; nn < 4; nn++)
                        mma_tf32(c[m][nn], a[m],
                                 Bf[kk][half*4 + nn][0], Bf[kk][half*4 + nn][1]);
            }

            // ---- scatter: lane holds (row, col..col+1) per fragment ----
#pragma unroll
            for (int m = 0; m < 2; m++) {
                const int r0  = m * 16 + gid;
                const int ro0 = __shfl_sync(0xffffffffu, orow, r0);
                const int ro1 = __shfl_sync(0xffffffffu, orow, r0 + 8);
#pragma unroll
                for (int nn = 0; nn < 4; nn++) {
                    const int col = half * 32 + nn * 8 + 2 * tig;
                    red_add_v2(out + (long long)ro0 * COUT + col,
                               c[m][nn][0], c[m][nn][1]);
                    red_add_v2(out + (long long)ro1 * COUT + col,
                               c[m][nn][2], c[m][nn][3]);
                }
            }
        }
        __syncwarp();                       // stage reuse safety

        cur_ir = nxt_ir;  cur_or = nxt_or;
        nxt_ir = pf_ir;   nxt_or = pf_or;
        unsigned int ts = sbuf_cur; sbuf_cur = sbuf_nxt; sbuf_nxt = ts;
        const float* tp = st_cur; st_cur = st_nxt; st_nxt = tp;
    }
}

// GroupNorm stats: 2 float4 rows per thread per iteration (double MLP).
__global__ void stats_kernel(const float4* __restrict__ out) {
    const int c4   = threadIdx.x & 15;
    const int ty   = threadIdx.x >> 4;
    const int lane = threadIdx.x & 31;
    __shared__ float s_sum[NGRP], s_sq[NGRP];
    if (threadIdx.x < NGRP) { s_sum[threadIdx.x] = 0.f; s_sq[threadIdx.x] = 0.f; }
    __syncthreads();

    float sum = 0.f, sq = 0.f;
    for (int row = blockIdx.x * 32 + ty; row < NPTS; row += gridDim.x * 32) {
        float4 v = __ldg(out + row * 16 + c4);
        int row2 = row + 16;
        if (row2 < NPTS) {
            float4 u = __ldg(out + row2 * 16 + c4);
            sum += (u.x + u.y) + (u.z + u.w);
            sq   = fmaf(u.x, u.x, fmaf(u.y, u.y, fmaf(u.z, u.z, fmaf(u.w, u.w, sq))));
        }
        sum += (v.x + v.y) + (v.z + v.w);
        sq   = fmaf(v.x, v.x, fmaf(v.y, v.y, fmaf(v.z, v.z, fmaf(v.w, v.w, sq))));
    }
    // lanes {2g, 2g+1, 2g+16, 2g+17} share group g
    sum += __shfl_xor_sync(0xffffffffu, sum, 16);
    sq  += __shfl_xor_sync(0xffffffffu, sq,  16);
    sum += __shfl_xor_sync(0xffffffffu, sum, 1);
    sq  += __shfl_xor_sync(0xffffffffu, sq,  1);
    if (lane < 16 && !(lane & 1)) {
        atomicAdd(&s_sum[lane >> 1], sum);
        atomicAdd(&s_sq[lane >> 1],  sq);
    }
    __syncthreads();
    if (threadIdx.x < NGRP) {
        atomicAdd(&g_sum[threadIdx.x], s_sum[threadIdx.x]);
        atomicAdd(&g_sq[threadIdx.x],  s_sq[threadIdx.x]);
    }
}

__device__ __forceinline__ float4 aff_lrelu(float4 v, float4 ga, float4 be) {
    v.x = fmaf(v.x, ga.x, be.x); v.x = (v.x >= 0.f) ? v.x : 0.01f * v.x;
    v.y = fmaf(v.y, ga.y, be.y); v.y = (v.y >= 0.f) ? v.y : 0.01f * v.y;
    v.z = fmaf(v.z, ga.z, be.z); v.z = (v.z >= 0.f) ? v.z : 0.01f * v.z;
    v.w = fmaf(v.w, ga.w, be.w); v.w = (v.w >= 0.f) ? v.w : 0.01f * v.w;
    return v;
}

// Fused finalize + affine + LeakyReLU: mean/inv computed inline from the
// global accumulators (kernel boundary after stats_kernel is the sync).
__global__ void norm_kernel(float4* __restrict__ out,
                            const float4* __restrict__ gamma4,
                            const float4* __restrict__ beta4) {
    const int c4 = threadIdx.x & 15;
    const int ty = threadIdx.x >> 4;
    const int g  = c4 >> 1;
    const float cnt = (float)NPTS * (COUT / NGRP);
    const float m   = g_sum[g] / cnt;
    const float var = g_sq[g] / cnt - m * m;
    const float inv = rsqrtf(var + 1e-5f);
    float4 ga = __ldg(gamma4 + c4);
    float4 be = __ldg(beta4  + c4);
    ga.x *= inv; ga.y *= inv; ga.z *= inv; ga.w *= inv;
    be.x -= m * ga.x; be.y -= m * ga.y; be.z -= m * ga.z; be.w -= m * ga.w;
    for (int row = blockIdx.x * 32 + ty; row < NPTS; row += gridDim.x * 32) {
        float4 v = out[row * 16 + c4];
        int row2 = row + 16;
        float4 u;
        bool has2 = (row2 < NPTS);
        if (has2) u = out[row2 * 16 + c4];
        out[row * 16 + c4] = aff_lrelu(v, ga, be);
        if (has2) out[row2 * 16 + c4] = aff_lrelu(u, ga, be);
    }
}

extern "C" void kernel_launch(void* const* d_in, const int* in_sizes, int n_in,
                              void* d_out, int out_size) {
    const float* feats   = (const float*)d_in[0];
    const float* weight  = (const float*)d_in[1];
    const float* gamma   = (const float*)d_in[2];
    const float* beta    = (const float*)d_in[3];
    const void*  in_idx  = d_in[4];
    const void*  out_idx = d_in[5];
    float* out = (float*)d_out;

    const int n4 = NPTS * COUT / 4;
    zero_kernel<<<(n4 + 255) / 256, 256>>>((float4*)out, n4,
                                           (const unsigned int*)in_idx);

    const int warps_per_k  = (NBATCH + NB - 1) / NB;          // 625
    const int blocks_per_k = (warps_per_k + 3) / 4;           // 157
    dim3 cgrid(blocks_per_k, KOFF);
    conv_kernel<<<cgrid, 128>>>(feats, weight, in_idx, out_idx, out);

    stats_kernel<<<1184, 256>>>((const float4*)out);
    norm_kernel<<<1184, 256>>>((float4*)out, (const float4*)gamma, (const float4*)beta);
}

// round 17
// speedup vs baseline: 1.6351x; 1.6351x over previous
#include <cuda_runtime.h>
#include <cstdint>

#define NPTS   300000
#define NPAIRS 100000
#define KOFF   27
#define CIN    32
#define COUT   64
#define NGRP   8
#define NB     5            // batches (of 32 pairs) per warp
#define NBATCH 3125         // 32-pair batches per k-offset (100000/32)
#define ROWPAD 36           // stage row stride in floats (conflict-free LDS)

// ---- scratch (no allocations allowed) ----
__device__ float g_sum[NGRP];
__device__ float g_sq[NGRP];
__device__ int   g_is64;

// tf32 round-to-nearest-even via integer ops (no cvt.*.tf32 instruction):
// keep top 19 bits (1s + 8e + 10m), RN-even on the 13 dropped bits.
__device__ __forceinline__ uint32_t to_tf32(float f) {
    uint32_t u = __float_as_uint(f);
    u += 0xFFFu + ((u >> 13) & 1u);
    return u & 0xFFFFE000u;
}

__device__ __forceinline__ void mma_tf32(float* c, const uint32_t* a,
                                         uint32_t b0, uint32_t b1) {
    asm volatile(
        "mma.sync.aligned.m16n8k8.row.col.f32.tf32.tf32.f32 "
        "{%0,%1,%2,%3}, {%4,%5,%6,%7}, {%8,%9}, {%0,%1,%2,%3};"
        : "+f"(c[0]), "+f"(c[1]), "+f"(c[2]), "+f"(c[3])
        : "r"(a[0]), "r"(a[1]), "r"(a[2]), "r"(a[3]), "r"(b0), "r"(b1));
}

__device__ __forceinline__ void red_add_v2(float* addr, float x, float y) {
    asm volatile("red.global.add.v2.f32 [%0], {%1, %2};"
                 :: "l"(addr), "f"(x), "f"(y) : "memory");
}

__device__ __forceinline__ void cp_async16(unsigned int saddr, const void* gptr) {
    asm volatile("cp.async.cg.shared.global [%0], [%1], 16;"
                 :: "r"(saddr), "l"(gptr) : "memory");
}
#define CP_COMMIT() asm volatile("cp.async.commit_group;" ::: "memory")
#define CP_WAIT1()  asm volatile("cp.async.wait_group 1;"  ::: "memory")

// zero output + scratch; block 0 also detects int64-vs-int32 indices
// (jax x64 ambiguity: if int64, high words of first 4K entries are all 0).
__global__ void zero_kernel(float4* __restrict__ out, int n4,
                            const unsigned int* __restrict__ idx32) {
    int i = blockIdx.x * blockDim.x + threadIdx.x;
    if (i < n4) out[i] = make_float4(0.f, 0.f, 0.f, 0.f);
    if (blockIdx.x == 0) {
        __shared__ int s_any;
        if (threadIdx.x == 0) s_any = 0;
        __syncthreads();
        unsigned int v = 0;
        for (int t = threadIdx.x; t < 2048; t += blockDim.x)
            v |= idx32[2 * t + 1];
        if (v) atomicOr(&s_any, 1);
        __syncthreads();
        if (threadIdx.x == 0) g_is64 = (s_any == 0) ? 1 : 0;
        if (threadIdx.x < NGRP) { g_sum[threadIdx.x] = 0.f; g_sq[threadIdx.x] = 0.f; }
    }
}

__device__ __forceinline__ int load_idx(const void* p, long long pos, int is64) {
    if (is64) return (int)((const long long*)p)[pos];
    return ((const int*)p)[pos];
}

// Sparse conv on tensor cores. Each warp owns NB=5 consecutive 32-pair
// batches; per batch, C[32,64] = A[32 pairs, 32 cin] x W[32,64] via 64
// mma.sync.m16n8k8.tf32 (2 HMMA/record).
//  - B fragments live in SMEM (8 KB, fragment-ordered, filled once per
//    block) -> 1 conflict-free LDS.64 per mma; frees 64 registers (no spill).
//  - A fragments loaded + converted ONCE per batch (32 regs), reused by
//    both n-halves.
//  - cp.async double-buffer streams the next batch's rows during compute.
// Scatter: C frags map to (row, 2 adjacent cols) -> red.global.add.v2.f32.
__global__ __launch_bounds__(128, 4)
void conv_kernel(const float* __restrict__ feats,
                 const float* __restrict__ weight,
                 const void*  __restrict__ in_idx,
                 const void*  __restrict__ out_idx,
                 float*       __restrict__ out) {
    const int k    = blockIdx.y;
    const int lane = threadIdx.x & 31;
    const int warp = threadIdx.x >> 5;

    __shared__ float stage[4][2][32 * ROWPAD];   // 36 KB: warp x buf x rows
    __shared__ uint2 Bsm[32 * 32];               // 8 KB: 32 frags x 32 lanes

    // ---- fill B fragment smem (whole block; one k-offset per block) ----
    const float* wk = weight + (long long)k * CIN * COUT;
    for (int i = 0; i < 8; i++) {
        const int f    = threadIdx.x + i * 128;  // 0..1023
        const int frag = f >> 5;                 // kk*8+nn, 0..31
        const int ln   = f & 31;
        const int kk   = frag >> 3;
        const int nn   = frag & 7;
        const int tg   = ln & 3;
        const int gd   = ln >> 2;
        uint2 bv;
        bv.x = to_tf32(__ldg(wk + (kk*8 + tg)     * COUT + nn*8 + gd));
        bv.y = to_tf32(__ldg(wk + (kk*8 + tg + 4) * COUT + nn*8 + gd));
        Bsm[frag * 32 + ln] = bv;
    }
    __syncthreads();

    const int b0 = (blockIdx.x * 4 + warp) * NB;
    if (b0 >= NBATCH) return;

    const int gid = lane >> 2;       // 0..7  (fragment group id)
    const int tig = lane & 3;        // 0..3  (thread in group)

    const int is64 = g_is64;
    const long long base = (long long)k * NPAIRS;
    const int sub = lane >> 3;          // row-within-group of 4 (cp.async)
    const int q   = lane & 7;           // 16B chunk within row (cp.async)
    const unsigned int sb0 = (unsigned int)__cvta_generic_to_shared(&stage[warp][0][0]);
    const unsigned int sb1 = (unsigned int)__cvta_generic_to_shared(&stage[warp][1][0]);

    auto idx_pos = [&](int b) -> long long {
        int bc = (b < NBATCH) ? b : NBATCH - 1;
        return base + bc * 32 + lane;
    };
    auto issue = [&](int ir, unsigned int sbuf) {
#pragma unroll
        for (int g = 0; g < 8; g++) {
            const int r    = 4 * g + sub;
            const int irow = __shfl_sync(0xffffffffu, ir, r);
            cp_async16(sbuf + r * (ROWPAD * 4) + q * 16,
                       (const char*)(feats + (long long)irow * CIN) + q * 16);
        }
    };

    // ---- prologue ----
    int cur_ir = load_idx(in_idx,  idx_pos(b0), is64);
    int cur_or = load_idx(out_idx, idx_pos(b0), is64);
    issue(cur_ir, sb0);
    CP_COMMIT();
    int nxt_ir = load_idx(in_idx,  idx_pos(b0 + 1), is64);
    int nxt_or = load_idx(out_idx, idx_pos(b0 + 1), is64);

    unsigned int sbuf_cur = sb0, sbuf_nxt = sb1;
    const float* st_cur = &stage[warp][0][0];
    const float* st_nxt = &stage[warp][1][0];

    for (int t = 0; t < NB; t++) {
        const int b = b0 + t;
        if (b >= NBATCH) break;

        if (t + 1 < NB && b + 1 < NBATCH) issue(nxt_ir, sbuf_nxt);
        CP_COMMIT();

        int pf_ir = load_idx(in_idx,  idx_pos(b + 2), is64);
        int pf_or = load_idx(out_idx, idx_pos(b + 2), is64);

        CP_WAIT1();
        __syncwarp();

        // ---- load + convert ALL A fragments once (reused by both halves) ----
        uint32_t a_all[4][2][4];
#pragma unroll
        for (int kk = 0; kk < 4; kk++) {
            const int cb = kk * 8 + tig;
#pragma unroll
            for (int m = 0; m < 2; m++) {
                const int r = m * 16 + gid;
                a_all[kk][m][0] = to_tf32(st_cur[r       * ROWPAD + cb]);
                a_all[kk][m][1] = to_tf32(st_cur[(r + 8) * ROWPAD + cb]);
                a_all[kk][m][2] = to_tf32(st_cur[r       * ROWPAD + cb + 4]);
                a_all[kk][m][3] = to_tf32(st_cur[(r + 8) * ROWPAD + cb + 4]);
            }
        }

        // ---- compute batch t on tensor cores, N in two halves ----
        const int orow = cur_or;
#pragma unroll
        for (int half = 0; half < 2; half++) {
            float c[2][4][4];
#pragma unroll
            for (int m = 0; m < 2; m++)
#pragma unroll
                for (int nn = 0; nn < 4; nn++)
#pragma unroll
                    for (int e = 0; e < 4; e++) c[m][nn][e] = 0.f;

#pragma unroll
            for (int kk = 0; kk < 4; kk++)
#pragma unroll
                for (int nn = 0; nn < 4; nn++) {
                    const uint2 bv = Bsm[((kk << 3) | (half*4 + nn)) * 32 + lane];
#pragma unroll
                    for (int m = 0; m < 2; m++)
                        mma_tf32(c[m][nn], a_all[kk][m], bv.x, bv.y);
                }

            // ---- scatter: lane holds (row, col..col+1) per fragment ----
#pragma unroll
            for (int m = 0; m < 2; m++) {
                const int r0  = m * 16 + gid;
                const int ro0 = __shfl_sync(0xffffffffu, orow, r0);
                const int ro1 = __shfl_sync(0xffffffffu, orow, r0 + 8);
#pragma unroll
                for (int nn = 0; nn < 4; nn++) {
                    const int col = half * 32 + nn * 8 + 2 * tig;
                    red_add_v2(out + (long long)ro0 * COUT + col,
                               c[m][nn][0], c[m][nn][1]);
                    red_add_v2(out + (long long)ro1 * COUT + col,
                               c[m][nn][2], c[m][nn][3]);
                }
            }
        }
        __syncwarp();                       // stage reuse safety

        cur_ir = nxt_ir;  cur_or = nxt_or;
        nxt_ir = pf_ir;   nxt_or = pf_or;
        unsigned int ts = sbuf_cur; sbuf_cur = sbuf_nxt; sbuf_nxt = ts;
        const float* tp = st_cur; st_cur = st_nxt; st_nxt = tp;
    }
}

// GroupNorm stats: 2 float4 rows per thread per iteration (double MLP).
__global__ void stats_kernel(const float4* __restrict__ out) {
    const int c4   = threadIdx.x & 15;
    const int ty   = threadIdx.x >> 4;
    const int lane = threadIdx.x & 31;
    __shared__ float s_sum[NGRP], s_sq[NGRP];
    if (threadIdx.x < NGRP) { s_sum[threadIdx.x] = 0.f; s_sq[threadIdx.x] = 0.f; }
    __syncthreads();

    float sum = 0.f, sq = 0.f;
    for (int row = blockIdx.x * 32 + ty; row < NPTS; row += gridDim.x * 32) {
        float4 v = __ldg(out + row * 16 + c4);
        int row2 = row + 16;
        if (row2 < NPTS) {
            float4 u = __ldg(out + row2 * 16 + c4);
            sum += (u.x + u.y) + (u.z + u.w);
            sq   = fmaf(u.x, u.x, fmaf(u.y, u.y, fmaf(u.z, u.z, fmaf(u.w, u.w, sq))));
        }
        sum += (v.x + v.y) + (v.z + v.w);
        sq   = fmaf(v.x, v.x, fmaf(v.y, v.y, fmaf(v.z, v.z, fmaf(v.w, v.w, sq))));
    }
    // lanes {2g, 2g+1, 2g+16, 2g+17} share group g
    sum += __shfl_xor_sync(0xffffffffu, sum, 16);
    sq  += __shfl_xor_sync(0xffffffffu, sq,  16);
    sum += __shfl_xor_sync(0xffffffffu, sum, 1);
    sq  += __shfl_xor_sync(0xffffffffu, sq,  1);
    if (lane < 16 && !(lane & 1)) {
        atomicAdd(&s_sum[lane >> 1], sum);
        atomicAdd(&s_sq[lane >> 1],  sq);
    }
    __syncthreads();
    if (threadIdx.x < NGRP) {
        atomicAdd(&g_sum[threadIdx.x], s_sum[threadIdx.x]);
        atomicAdd(&g_sq[threadIdx.x],  s_sq[threadIdx.x]);
    }
}

__device__ __forceinline__ float4 aff_lrelu(float4 v, float4 ga, float4 be) {
    v.x = fmaf(v.x, ga.x, be.x); v.x = (v.x >= 0.f) ? v.x : 0.01f * v.x;
    v.y = fmaf(v.y, ga.y, be.y); v.y = (v.y >= 0.f) ? v.y : 0.01f * v.y;
    v.z = fmaf(v.z, ga.z, be.z); v.z = (v.z >= 0.f) ? v.z : 0.01f * v.z;
    v.w = fmaf(v.w, ga.w, be.w); v.w = (v.w >= 0.f) ? v.w : 0.01f * v.w;
    return v;
}

// Fused finalize + affine + LeakyReLU: mean/inv computed inline from the
// global accumulators (kernel boundary after stats_kernel is the sync).
__global__ void norm_kernel(float4* __restrict__ out,
                            const float4* __restrict__ gamma4,
                            const float4* __restrict__ beta4) {
    const int c4 = threadIdx.x & 15;
    const int ty = threadIdx.x >> 4;
    const int g  = c4 >> 1;
    const float cnt = (float)NPTS * (COUT / NGRP);
    const float m   = g_sum[g] / cnt;
    const float var = g_sq[g] / cnt - m * m;
    const float inv = rsqrtf(var + 1e-5f);
    float4 ga = __ldg(gamma4 + c4);
    float4 be = __ldg(beta4  + c4);
    ga.x *= inv; ga.y *= inv; ga.z *= inv; ga.w *= inv;
    be.x -= m * ga.x; be.y -= m * ga.y; be.z -= m * ga.z; be.w -= m * ga.w;
    for (int row = blockIdx.x * 32 + ty; row < NPTS; row += gridDim.x * 32) {
        float4 v = out[row * 16 + c4];
        int row2 = row + 16;
        float4 u;
        bool has2 = (row2 < NPTS);
        if (has2) u = out[row2 * 16 + c4];
        out[row * 16 + c4] = aff_lrelu(v, ga, be);
        if (has2) out[row2 * 16 + c4] = aff_lrelu(u, ga, be);
    }
}

extern "C" void kernel_launch(void* const* d_in, const int* in_sizes, int n_in,
                              void* d_out, int out_size) {
    const float* feats   = (const float*)d_in[0];
    const float* weight  = (const float*)d_in[1];
    const float* gamma   = (const float*)d_in[2];
    const float* beta    = (const float*)d_in[3];
    const void*  in_idx  = d_in[4];
    const void*  out_idx = d_in[5];
    float* out = (float*)d_out;

    const int n4 = NPTS * COUT / 4;
    zero_kernel<<<(n4 + 255) / 256, 256>>>((float4*)out, n4,
                                           (const unsigned int*)in_idx);

    const int warps_per_k  = (NBATCH + NB - 1) / NB;          // 625
    const int blocks_per_k = (warps_per_k + 3) / 4;           // 157
    dim3 cgrid(blocks_per_k, KOFF);
    conv_kernel<<<cgrid, 128>>>(feats, weight, in_idx, out_idx, out);

    stats_kernel<<<1184, 256>>>((const float4*)out);
    norm_kernel<<<1184, 256>>>((float4*)out, (const float4*)gamma, (const float4*)beta);
}